// round 11
// baseline (speedup 1.0000x reference)
#include <cuda_runtime.h>
#include <cuda_bf16.h>
#include <cstdint>

#define NFEAT 1024
#define NHEAD 16
#define DK    64
#define BATCH 4
#define TSEQ  1024
#define MTOT  (BATCH * TSEQ)   // 4096

// ---------------------------------------------------------------------------
// Scratch (device globals — no allocations allowed)
// ---------------------------------------------------------------------------
__device__ int g_mask_byte;

// bf16 hi/lo split operands
__device__ __nv_bfloat16 g_inh[3][MTOT * NFEAT];   // query,key,value inputs hi
__device__ __nv_bfloat16 g_inl[3][MTOT * NFEAT];   // lo
__device__ __nv_bfloat16 g_wth[4][NFEAT * NFEAT];  // W^T hi (q,k,v,o) [n][k]
__device__ __nv_bfloat16 g_wtl[4][NFEAT * NFEAT];  // W^T lo
// projected Q/K/V (bf16 split, written by GEMM epilogue)
__device__ __nv_bfloat16 g_qh[MTOT * NFEAT], g_ql[MTOT * NFEAT];
__device__ __nv_bfloat16 g_kh[MTOT * NFEAT], g_kl[MTOT * NFEAT];
__device__ __nv_bfloat16 g_vh[MTOT * NFEAT], g_vl[MTOT * NFEAT];
// attention output (bf16 split, consumed by O-proj)
__device__ __nv_bfloat16 g_xh[MTOT * NFEAT], g_xl[MTOT * NFEAT];

// ---------------------------------------------------------------------------
// Portable PTX helpers (generic compute_103-legal)
// ---------------------------------------------------------------------------
__device__ __forceinline__ uint32_t smem_u32(const void* p) {
    uint32_t a;
    asm("{ .reg .u64 t; cvta.to.shared.u64 t, %1; cvt.u32.u64 %0, t; }"
        : "=r"(a) : "l"(p));
    return a;
}
__device__ __forceinline__ void cpa16(uint32_t saddr, const void* gaddr) {
    asm volatile("cp.async.cg.shared.global [%0], [%1], 16;"
                 :: "r"(saddr), "l"(gaddr) : "memory");
}
#define CPA_COMMIT() asm volatile("cp.async.commit_group;" ::: "memory")
#define CPA_WAIT(n)  asm volatile("cp.async.wait_group %0;" :: "n"(n) : "memory")

#define MMA16816(d, a, b)                                                     \
    asm volatile("mma.sync.aligned.m16n8k16.row.col.f32.bf16.bf16.f32 "       \
                 "{%0,%1,%2,%3}, {%4,%5,%6,%7}, {%8,%9}, {%0,%1,%2,%3};"      \
                 : "+f"((d)[0]), "+f"((d)[1]), "+f"((d)[2]), "+f"((d)[3])     \
                 : "r"((a)[0]), "r"((a)[1]), "r"((a)[2]), "r"((a)[3]),        \
                   "r"((b)[0]), "r"((b)[1]))

__device__ __forceinline__ void ldm_x4(uint32_t* r, uint32_t a) {
    asm volatile("ldmatrix.sync.aligned.m8n8.x4.shared.b16 {%0,%1,%2,%3}, [%4];"
                 : "=r"(r[0]), "=r"(r[1]), "=r"(r[2]), "=r"(r[3]) : "r"(a));
}
__device__ __forceinline__ void ldm_x2(uint32_t* r, uint32_t a) {
    asm volatile("ldmatrix.sync.aligned.m8n8.x2.shared.b16 {%0,%1}, [%2];"
                 : "=r"(r[0]), "=r"(r[1]) : "r"(a));
}
__device__ __forceinline__ void ldm_x2t(uint32_t* r, uint32_t a) {
    asm volatile("ldmatrix.sync.aligned.m8n8.x2.trans.shared.b16 {%0,%1}, [%2];"
                 : "=r"(r[0]), "=r"(r[1]) : "r"(a));
}

__device__ __forceinline__ void store_split2(__nv_bfloat16* Ch, __nv_bfloat16* Cl,
                                             size_t off, float v0, float v1) {
    __nv_bfloat16 h0 = __float2bfloat16(v0), h1 = __float2bfloat16(v1);
    __nv_bfloat162 hh; hh.x = h0; hh.y = h1;
    *(__nv_bfloat162*)(Ch + off) = hh;
    __nv_bfloat162 ll;
    ll.x = __float2bfloat16(v0 - __bfloat162float(h0));
    ll.y = __float2bfloat16(v1 - __bfloat162float(h1));
    *(__nv_bfloat162*)(Cl + off) = ll;
}

// ---------------------------------------------------------------------------
// Mask dtype detection
// ---------------------------------------------------------------------------
__global__ void detect_mask_kernel(const uint32_t* __restrict__ m) {
    __shared__ int flag;
    if (threadIdx.x == 0) flag = 0;
    __syncthreads();
    for (int i = threadIdx.x; i < 1024; i += blockDim.x) {
        uint32_t w = m[i];
        if (w != 0u && w != 1u && w != 0x3F800000u) flag = 1;
    }
    __syncthreads();
    if (threadIdx.x == 0) g_mask_byte = flag;
}

// ---------------------------------------------------------------------------
// hi/lo split conversions
// ---------------------------------------------------------------------------
__device__ __forceinline__ void split4(const float4 v, __nv_bfloat16* h, __nv_bfloat16* l) {
    float a[4] = {v.x, v.y, v.z, v.w};
    #pragma unroll
    for (int j = 0; j < 4; j++) {
        __nv_bfloat16 hi = __float2bfloat16(a[j]);
        h[j] = hi;
        l[j] = __float2bfloat16(a[j] - __bfloat162float(hi));
    }
}

__global__ void split_inputs_kernel(const float* __restrict__ q,
                                    const float* __restrict__ k,
                                    const float* __restrict__ v) {
    int z = blockIdx.y;
    const float* src = (z == 0) ? q : (z == 1) ? k : v;
    size_t i4 = (size_t)blockIdx.x * blockDim.x + threadIdx.x;
    float4 val = ((const float4*)src)[i4];
    __nv_bfloat16 h[4], l[4];
    split4(val, h, l);
    *(uint2*)&g_inh[z][i4 * 4] = *(uint2*)h;
    *(uint2*)&g_inl[z][i4 * 4] = *(uint2*)l;
}

// Transposed split of weights: g_wt*[w][n*1024+k] = split(W[k*1024+n])
__global__ void split_weights_kernel(const float* __restrict__ Wq,
                                     const float* __restrict__ Wk,
                                     const float* __restrict__ Wv,
                                     const float* __restrict__ Wo) {
    __shared__ float tile[32][33];
    int w = blockIdx.z;
    const float* W = (w == 0) ? Wq : (w == 1) ? Wk : (w == 2) ? Wv : Wo;
    int n0 = blockIdx.x * 32, k0 = blockIdx.y * 32;
    int tx = threadIdx.x, ty = threadIdx.y;
    #pragma unroll
    for (int r = 0; r < 32; r += 8)
        tile[ty + r][tx] = W[(size_t)(k0 + ty + r) * 1024 + n0 + tx];
    __syncthreads();
    #pragma unroll
    for (int r = 0; r < 32; r += 8) {
        float a = tile[tx][ty + r];
        __nv_bfloat16 hi = __float2bfloat16(a);
        size_t off = (size_t)(n0 + ty + r) * 1024 + k0 + tx;
        g_wth[w][off] = hi;
        g_wtl[w][off] = __float2bfloat16(a - __bfloat162float(hi));
    }
}

// ---------------------------------------------------------------------------
// HMMA bf16-split GEMM: C[4096x1024] = A @ W + bias
// CTA tile 128x128, K-chunks of 32, cp.async double buffer, 8 warps (2x4),
// warp tile 64x32, ldmatrix fragment loads (80B stride = conflict-free).
// Epilogue: fp32 out (Cf) OR bf16 hi/lo split (Ch/Cl).
// ---------------------------------------------------------------------------
#define ROWB      80
#define ARR_B     (128 * ROWB)
#define STAGE_B   (4 * ARR_B)
#define GEMM_SMEM (2 * STAGE_B)

__device__ __forceinline__ void gemm_issue_loads(
    uint32_t sbase, int buf, int tid, int bm, int bn, int k0,
    const __nv_bfloat16* Ah, const __nv_bfloat16* Al,
    const __nv_bfloat16* Bh, const __nv_bfloat16* Bl)
{
    #pragma unroll
    for (int t = 0; t < 2; t++) {
        int id = tid + t * 256;
        int r  = id >> 2;
        int gg = (id & 3) * 8;
        uint32_t so = (uint32_t)buf * STAGE_B + (uint32_t)r * ROWB + gg * 2;
        size_t goA = (size_t)(bm + r) * 1024 + k0 + gg;
        size_t goB = (size_t)(bn + r) * 1024 + k0 + gg;
        cpa16(sbase + so + 0 * ARR_B, Ah + goA);
        cpa16(sbase + so + 1 * ARR_B, Al + goA);
        cpa16(sbase + so + 2 * ARR_B, Bh + goB);
        cpa16(sbase + so + 3 * ARR_B, Bl + goB);
    }
}

__device__ __forceinline__ void gemm_hmma_body(
    const __nv_bfloat16* __restrict__ Ah, const __nv_bfloat16* __restrict__ Al,
    const __nv_bfloat16* __restrict__ Bh, const __nv_bfloat16* __restrict__ Bl,
    const float* __restrict__ bias,
    float* Cf, __nv_bfloat16* Ch, __nv_bfloat16* Cl)
{
    extern __shared__ char dsm[];
    const uint32_t sbase = smem_u32(dsm);
    const int tid  = threadIdx.x;
    const int warp = tid >> 5;
    const int lane = tid & 31;
    const int g    = lane >> 2;
    const int tig  = lane & 3;
    const int wm   = warp >> 2;
    const int wn   = warp & 3;
    const int bm = blockIdx.y * 128;
    const int bn = blockIdx.x * 128;
    const int lane7 = lane & 7;
    const int xr = lane7 + ((lane >> 3) & 1) * 8;
    const int xc = (lane >> 4) * 16;
    const int b16o = ((lane >> 3) & 1) * 16;

    float acc[4][4][4];
    #pragma unroll
    for (int mt = 0; mt < 4; mt++)
        #pragma unroll
        for (int nt = 0; nt < 4; nt++)
            #pragma unroll
            for (int e = 0; e < 4; e++) acc[mt][nt][e] = 0.0f;

    gemm_issue_loads(sbase, 0, tid, bm, bn, 0, Ah, Al, Bh, Bl);
    CPA_COMMIT();

    for (int c = 0; c < 32; c++) {
        const int buf = c & 1;
        if (c + 1 < 32) {
            gemm_issue_loads(sbase, (c + 1) & 1, tid, bm, bn, (c + 1) * 32,
                             Ah, Al, Bh, Bl);
            CPA_COMMIT();
            CPA_WAIT(1);
        } else {
            CPA_WAIT(0);
        }
        __syncthreads();

        const uint32_t sA = sbase + buf * STAGE_B;
        const uint32_t sB = sA + 2 * ARR_B;
        const uint32_t aOff = sA + (wm * 64 + xr) * ROWB + xc;
        const uint32_t bOff = sB + (wn * 32 + lane7) * ROWB + b16o;

        #pragma unroll
        for (int s = 0; s < 2; s++) {
            const int sb = s * 32;
            uint32_t ah[4][4], al[4][4], bh[4][2], bl[4][2];
            #pragma unroll
            for (int mt = 0; mt < 4; mt++) {
                ldm_x4(ah[mt], aOff + mt * 16 * ROWB + sb);
                ldm_x4(al[mt], aOff + ARR_B + mt * 16 * ROWB + sb);
            }
            #pragma unroll
            for (int nt = 0; nt < 4; nt++) {
                ldm_x2(bh[nt], bOff + nt * 8 * ROWB + sb);
                ldm_x2(bl[nt], bOff + ARR_B + nt * 8 * ROWB + sb);
            }
            #pragma unroll
            for (int mt = 0; mt < 4; mt++)
                #pragma unroll
                for (int nt = 0; nt < 4; nt++) {
                    MMA16816(acc[mt][nt], ah[mt], bh[nt]);
                    MMA16816(acc[mt][nt], ah[mt], bl[nt]);
                    MMA16816(acc[mt][nt], al[mt], bh[nt]);
                }
        }
        __syncthreads();
    }

    // epilogue
    #pragma unroll
    for (int nt = 0; nt < 4; nt++) {
        int col = bn + wn * 32 + nt * 8 + tig * 2;
        float2 bb = *(const float2*)&bias[col];
        #pragma unroll
        for (int mt = 0; mt < 4; mt++) {
            int row = bm + wm * 64 + mt * 16 + g;
            float v0 = acc[mt][nt][0] + bb.x, v1 = acc[mt][nt][1] + bb.y;
            float v2 = acc[mt][nt][2] + bb.x, v3 = acc[mt][nt][3] + bb.y;
            if (Cf) {
                *(float2*)&Cf[(size_t)row * 1024 + col] = make_float2(v0, v1);
                *(float2*)&Cf[(size_t)(row + 8) * 1024 + col] = make_float2(v2, v3);
            } else {
                store_split2(Ch, Cl, (size_t)row * 1024 + col, v0, v1);
                store_split2(Ch, Cl, (size_t)(row + 8) * 1024 + col, v2, v3);
            }
        }
    }
}

__global__ __launch_bounds__(256, 1)
void qkv_mma_kernel(const float* __restrict__ bq, const float* __restrict__ bk,
                    const float* __restrict__ bv)
{
    int z = blockIdx.z;
    const float* bias = (z == 0) ? bq : (z == 1) ? bk : bv;
    __nv_bfloat16* Ch = (z == 0) ? g_qh : (z == 1) ? g_kh : g_vh;
    __nv_bfloat16* Cl = (z == 0) ? g_ql : (z == 1) ? g_kl : g_vl;
    gemm_hmma_body(g_inh[z], g_inl[z], g_wth[z], g_wtl[z], bias,
                   nullptr, Ch, Cl);
}

__global__ __launch_bounds__(256, 1)
void o_mma_kernel(const float* __restrict__ bo, float* __restrict__ out)
{
    gemm_hmma_body(g_xh, g_xl, g_wth[3], g_wtl[3], bo, out, nullptr, nullptr);
}

// ---------------------------------------------------------------------------
// HMMA flash-attention. CTA = 128 q-rows x (head,batch); 8 warps, each owns
// 16 q-rows. K/V tiles of 128 rows double-buffered via cp.async. Q fragments
// register-resident. S = Qh*Kh + Qh*Kl + Ql*Kh; P split in-register;
// O += Ph*Vh + Ph*Vl + Pl*Vh. Epilogue writes X as bf16 hi/lo.
// ---------------------------------------------------------------------------
#define ASTR     144
#define AARR     (128 * ASTR)     // 18432
#define ATT_SMEM (10 * AARR)      // Qh,Ql + 2 x (Kh,Kl,Vh,Vl) = 184320

__device__ __forceinline__ void att_load_kv(uint32_t sbase, int tid, int b, int h,
                                            int kt, int buf)
{
    #pragma unroll
    for (int i = 0; i < 16; i++) {
        int id = tid + i * 256;           // 0..4095
        int arr = id >> 10;               // 0=Kh 1=Kl 2=Vh 3=Vl
        int r = (id >> 3) & 127, ck = id & 7;
        const __nv_bfloat16* base =
            (arr == 0) ? g_kh : (arr == 1) ? g_kl : (arr == 2) ? g_vh : g_vl;
        const __nv_bfloat16* src =
            base + (size_t)(b * 1024 + kt * 128 + r) * 1024 + h * 64 + ck * 8;
        cpa16(sbase + (uint32_t)(2 + buf * 4 + arr) * AARR + r * ASTR + ck * 16, src);
    }
    CPA_COMMIT();
}

__global__ __launch_bounds__(256, 1)
void attention_kernel(const void* __restrict__ maskp)
{
    extern __shared__ char att_sm[];
    const uint32_t sbase = smem_u32(att_sm);
    const int tid = threadIdx.x, warp = tid >> 5, lane = tid & 31;
    const int g = lane >> 2, tig = lane & 3;
    const int lane7 = lane & 7;
    const int qt = blockIdx.x, h = blockIdx.y, b = blockIdx.z;

    const bool mbyte = (g_mask_byte != 0);
    const uint8_t*  mask8  = (const uint8_t*)maskp;
    const uint32_t* mask32 = (const uint32_t*)maskp;

    // ---- async load Q tile (hi+lo) ----
    #pragma unroll
    for (int i = 0; i < 8; i++) {
        int id = tid + i * 256;           // 0..2047
        int arr = id >> 10;
        int r = (id >> 3) & 127, ck = id & 7;
        const __nv_bfloat16* src = (arr ? g_ql : g_qh)
            + (size_t)(b * 1024 + qt * 128 + r) * 1024 + h * 64 + ck * 8;
        cpa16(sbase + (uint32_t)arr * AARR + r * ASTR + ck * 16, src);
    }
    CPA_COMMIT();
    att_load_kv(sbase, tid, b, h, 0, 0);
    CPA_WAIT(1);               // Q group done (KV0 still pending)
    __syncthreads();

    // ---- Q fragments, register-resident for the whole kernel ----
    uint32_t qfh[4][4], qfl[4][4];
    {
        const int xr = lane7 + ((lane >> 3) & 1) * 8;
        const int xc = (lane >> 4) * 16;
        uint32_t qb = sbase + (warp * 16 + xr) * ASTR + xc;
        #pragma unroll
        for (int kc = 0; kc < 4; kc++) {
            ldm_x4(qfh[kc], qb + kc * 32);
            ldm_x4(qfl[kc], qb + AARR + kc * 32);
        }
    }

    float O[8][4];
    #pragma unroll
    for (int nt = 0; nt < 8; nt++)
        #pragma unroll
        for (int e = 0; e < 4; e++) O[nt][e] = 0.0f;
    float l0 = 0.f, l1 = 0.f;

    const uint32_t kAdd = lane7 * ASTR + ((lane >> 3) & 1) * 16;
    const uint32_t vAdd = (lane7 + ((lane >> 3) & 1) * 8) * ASTR;
    const size_t mbase = ((size_t)b * 1024 + qt * 128 + warp * 16 + g) * 1024;

    for (int kt = 0; kt < 8; kt++) {
        if (kt < 7) {
            att_load_kv(sbase, tid, b, h, kt + 1, (kt + 1) & 1);
            CPA_WAIT(1);
        } else {
            CPA_WAIT(0);
        }
        __syncthreads();

        const uint32_t kb = sbase + (uint32_t)(2 + (kt & 1) * 4) * AARR;
        const uint32_t vb = kb + 2 * AARR;

        #pragma unroll
        for (int n4 = 0; n4 < 16; n4 += 4) {
            // ---- S = Q K^T for 4 ntiles ----
            float S[4][4];
            #pragma unroll
            for (int u = 0; u < 4; u++)
                #pragma unroll
                for (int e = 0; e < 4; e++) S[u][e] = 0.0f;
            #pragma unroll
            for (int kc = 0; kc < 4; kc++) {
                uint32_t kh_[4][2], kl_[4][2];
                #pragma unroll
                for (int u = 0; u < 4; u++) {
                    uint32_t a = kb + (uint32_t)(n4 + u) * 8 * ASTR + kc * 32 + kAdd;
                    ldm_x2(kh_[u], a);
                    ldm_x2(kl_[u], a + AARR);
                }
                #pragma unroll
                for (int u = 0; u < 4; u++) MMA16816(S[u], qfh[kc], kh_[u]);
                #pragma unroll
                for (int u = 0; u < 4; u++) MMA16816(S[u], qfh[kc], kl_[u]);
                #pragma unroll
                for (int u = 0; u < 4; u++) MMA16816(S[u], qfl[kc], kh_[u]);
            }
            // ---- mask + exp + split into A fragments ----
            uint32_t ph4[4][2], pl4[4][2];
            #pragma unroll
            for (int u = 0; u < 4; u++) {
                int col = kt * 128 + (n4 + u) * 8 + tig * 2;
                size_t m0off = mbase + col;
                size_t m1off = m0off + 8 * 1024;
                uint32_t mm0, mm1, mm2, mm3;
                if (mbyte) {
                    uint16_t w0 = *(const uint16_t*)(mask8 + m0off);
                    uint16_t w1 = *(const uint16_t*)(mask8 + m1off);
                    mm0 = w0 & 0xffu; mm1 = w0 >> 8;
                    mm2 = w1 & 0xffu; mm3 = w1 >> 8;
                } else {
                    uint2 w0 = *(const uint2*)(mask32 + m0off);
                    uint2 w1 = *(const uint2*)(mask32 + m1off);
                    mm0 = w0.x; mm1 = w0.y; mm2 = w1.x; mm3 = w1.y;
                }
                float p0 = mm0 ? 0.f : __expf(S[u][0] * 0.125f);
                float p1 = mm1 ? 0.f : __expf(S[u][1] * 0.125f);
                float p2 = mm2 ? 0.f : __expf(S[u][2] * 0.125f);
                float p3 = mm3 ? 0.f : __expf(S[u][3] * 0.125f);
                l0 += p0 + p1;  l1 += p2 + p3;
                __nv_bfloat16 h0 = __float2bfloat16(p0), h1 = __float2bfloat16(p1);
                __nv_bfloat16 h2 = __float2bfloat16(p2), h3 = __float2bfloat16(p3);
                __nv_bfloat162 t;
                t.x = h0; t.y = h1; ph4[u][0] = *(uint32_t*)&t;
                t.x = h2; t.y = h3; ph4[u][1] = *(uint32_t*)&t;
                t.x = __float2bfloat16(p0 - __bfloat162float(h0));
                t.y = __float2bfloat16(p1 - __bfloat162float(h1));
                pl4[u][0] = *(uint32_t*)&t;
                t.x = __float2bfloat16(p2 - __bfloat162float(h2));
                t.y = __float2bfloat16(p3 - __bfloat162float(h3));
                pl4[u][1] = *(uint32_t*)&t;
            }
            // ---- O += P V for the 2 k16-chunks these 4 ntiles cover ----
            #pragma unroll
            for (int jj = 0; jj < 2; jj++) {
                int jc = n4 / 2 + jj;
                uint32_t ah[4] = {ph4[2*jj][0], ph4[2*jj][1],
                                  ph4[2*jj+1][0], ph4[2*jj+1][1]};
                uint32_t al[4] = {pl4[2*jj][0], pl4[2*jj][1],
                                  pl4[2*jj+1][0], pl4[2*jj+1][1]};
                #pragma unroll
                for (int nt = 0; nt < 8; nt++) {
                    uint32_t vh_[2], vl_[2];
                    uint32_t a = vb + (uint32_t)jc * 16 * ASTR + nt * 16 + vAdd;
                    ldm_x2t(vh_, a);
                    ldm_x2t(vl_, a + AARR);
                    MMA16816(O[nt], ah, vh_);
                    MMA16816(O[nt], ah, vl_);
                    MMA16816(O[nt], al, vh_);
                }
            }
        }
        __syncthreads();
    }

    // ---- normalize rows, write X (bf16 split) ----
    l0 += __shfl_xor_sync(0xffffffffu, l0, 1);
    l0 += __shfl_xor_sync(0xffffffffu, l0, 2);
    l1 += __shfl_xor_sync(0xffffffffu, l1, 1);
    l1 += __shfl_xor_sync(0xffffffffu, l1, 2);
    float inv0 = (l0 > 0.f) ? 1.f / l0 : 0.f;
    float inv1 = (l1 > 0.f) ? 1.f / l1 : 0.f;

    size_t row = (size_t)(b * 1024 + qt * 128 + warp * 16 + g);
    #pragma unroll
    for (int nt = 0; nt < 8; nt++) {
        int col = h * 64 + nt * 8 + tig * 2;
        store_split2(g_xh, g_xl, row * 1024 + col, O[nt][0] * inv0, O[nt][1] * inv0);
        store_split2(g_xh, g_xl, (row + 8) * 1024 + col, O[nt][2] * inv1, O[nt][3] * inv1);
    }
}

// ---------------------------------------------------------------------------
// Launch
// ---------------------------------------------------------------------------
extern "C" void kernel_launch(void* const* d_in, const int* in_sizes, int n_in,
                              void* d_out, int out_size)
{
    const float* query = (const float*)d_in[0];
    const float* key   = (const float*)d_in[1];
    const float* value = (const float*)d_in[2];
    const void*  mask  = d_in[3];
    const float* Wq = (const float*)d_in[4];
    const float* bq = (const float*)d_in[5];
    const float* Wk = (const float*)d_in[6];
    const float* bk = (const float*)d_in[7];
    const float* Wv = (const float*)d_in[8];
    const float* bv = (const float*)d_in[9];
    const float* Wo = (const float*)d_in[10];
    const float* bo = (const float*)d_in[11];
    float* out = (float*)d_out;

    cudaFuncSetAttribute(qkv_mma_kernel,
                         cudaFuncAttributeMaxDynamicSharedMemorySize, GEMM_SMEM);
    cudaFuncSetAttribute(o_mma_kernel,
                         cudaFuncAttributeMaxDynamicSharedMemorySize, GEMM_SMEM);
    cudaFuncSetAttribute(attention_kernel,
                         cudaFuncAttributeMaxDynamicSharedMemorySize, ATT_SMEM);

    detect_mask_kernel<<<1, 256>>>((const uint32_t*)mask);
    split_inputs_kernel<<<dim3(4096, 3), 256>>>(query, key, value);
    split_weights_kernel<<<dim3(32, 32, 4), dim3(32, 8)>>>(Wq, Wk, Wv, Wo);
    qkv_mma_kernel<<<dim3(8, 32, 3), 256, GEMM_SMEM>>>(bq, bk, bv);
    attention_kernel<<<dim3(8, NHEAD, BATCH), 256, ATT_SMEM>>>(mask);
    o_mma_kernel<<<dim3(8, 32, 1), 256, GEMM_SMEM>>>(bo, out);
}

// round 12
// speedup vs baseline: 1.0035x; 1.0035x over previous
#include <cuda_runtime.h>
#include <cuda_bf16.h>
#include <cstdint>

#define NFEAT 1024
#define NHEAD 16
#define DK    64
#define BATCH 4
#define TSEQ  1024
#define MTOT  (BATCH * TSEQ)   // 4096

// ---------------------------------------------------------------------------
// Scratch (device globals — no allocations allowed)
// ---------------------------------------------------------------------------
__device__ int g_mask_byte;

// bf16 hi/lo split operands
__device__ __nv_bfloat16 g_inh[3][MTOT * NFEAT];   // query,key,value inputs hi
__device__ __nv_bfloat16 g_inl[3][MTOT * NFEAT];   // lo
__device__ __nv_bfloat16 g_wth[4][NFEAT * NFEAT];  // W^T hi (q,k,v,o) [n][k]
__device__ __nv_bfloat16 g_wtl[4][NFEAT * NFEAT];  // W^T lo
// projected Q/K/V (bf16 split, written by GEMM epilogue)
__device__ __nv_bfloat16 g_qh[MTOT * NFEAT], g_ql[MTOT * NFEAT];
__device__ __nv_bfloat16 g_kh[MTOT * NFEAT], g_kl[MTOT * NFEAT];
__device__ __nv_bfloat16 g_vh[MTOT * NFEAT], g_vl[MTOT * NFEAT];
// attention output (bf16 split, consumed by O-proj)
__device__ __nv_bfloat16 g_xh[MTOT * NFEAT], g_xl[MTOT * NFEAT];

// ---------------------------------------------------------------------------
// Portable PTX helpers (generic compute_103-legal)
// ---------------------------------------------------------------------------
__device__ __forceinline__ uint32_t smem_u32(const void* p) {
    uint32_t a;
    asm("{ .reg .u64 t; cvta.to.shared.u64 t, %1; cvt.u32.u64 %0, t; }"
        : "=r"(a) : "l"(p));
    return a;
}
__device__ __forceinline__ void cpa16(uint32_t saddr, const void* gaddr) {
    asm volatile("cp.async.cg.shared.global [%0], [%1], 16;"
                 :: "r"(saddr), "l"(gaddr) : "memory");
}
#define CPA_COMMIT() asm volatile("cp.async.commit_group;" ::: "memory")
#define CPA_WAIT(n)  asm volatile("cp.async.wait_group %0;" :: "n"(n) : "memory")

#define MMA16816(d, a, b)                                                     \
    asm volatile("mma.sync.aligned.m16n8k16.row.col.f32.bf16.bf16.f32 "       \
                 "{%0,%1,%2,%3}, {%4,%5,%6,%7}, {%8,%9}, {%0,%1,%2,%3};"      \
                 : "+f"((d)[0]), "+f"((d)[1]), "+f"((d)[2]), "+f"((d)[3])     \
                 : "r"((a)[0]), "r"((a)[1]), "r"((a)[2]), "r"((a)[3]),        \
                   "r"((b)[0]), "r"((b)[1]))

__device__ __forceinline__ void ldm_x4(uint32_t* r, uint32_t a) {
    asm volatile("ldmatrix.sync.aligned.m8n8.x4.shared.b16 {%0,%1,%2,%3}, [%4];"
                 : "=r"(r[0]), "=r"(r[1]), "=r"(r[2]), "=r"(r[3]) : "r"(a));
}
__device__ __forceinline__ void ldm_x2(uint32_t* r, uint32_t a) {
    asm volatile("ldmatrix.sync.aligned.m8n8.x2.shared.b16 {%0,%1}, [%2];"
                 : "=r"(r[0]), "=r"(r[1]) : "r"(a));
}
__device__ __forceinline__ void ldm_x2t(uint32_t* r, uint32_t a) {
    asm volatile("ldmatrix.sync.aligned.m8n8.x2.trans.shared.b16 {%0,%1}, [%2];"
                 : "=r"(r[0]), "=r"(r[1]) : "r"(a));
}

__device__ __forceinline__ void store_split2(__nv_bfloat16* Ch, __nv_bfloat16* Cl,
                                             size_t off, float v0, float v1) {
    __nv_bfloat16 h0 = __float2bfloat16(v0), h1 = __float2bfloat16(v1);
    __nv_bfloat162 hh; hh.x = h0; hh.y = h1;
    *(__nv_bfloat162*)(Ch + off) = hh;
    __nv_bfloat162 ll;
    ll.x = __float2bfloat16(v0 - __bfloat162float(h0));
    ll.y = __float2bfloat16(v1 - __bfloat162float(h1));
    *(__nv_bfloat162*)(Cl + off) = ll;
}

// ---------------------------------------------------------------------------
// Mask dtype detection
// ---------------------------------------------------------------------------
__global__ void detect_mask_kernel(const uint32_t* __restrict__ m) {
    __shared__ int flag;
    if (threadIdx.x == 0) flag = 0;
    __syncthreads();
    for (int i = threadIdx.x; i < 1024; i += blockDim.x) {
        uint32_t w = m[i];
        if (w != 0u && w != 1u && w != 0x3F800000u) flag = 1;
    }
    __syncthreads();
    if (threadIdx.x == 0) g_mask_byte = flag;
}

// ---------------------------------------------------------------------------
// hi/lo split conversions
// ---------------------------------------------------------------------------
__device__ __forceinline__ void split4(const float4 v, __nv_bfloat16* h, __nv_bfloat16* l) {
    float a[4] = {v.x, v.y, v.z, v.w};
    #pragma unroll
    for (int j = 0; j < 4; j++) {
        __nv_bfloat16 hi = __float2bfloat16(a[j]);
        h[j] = hi;
        l[j] = __float2bfloat16(a[j] - __bfloat162float(hi));
    }
}

__global__ void split_inputs_kernel(const float* __restrict__ q,
                                    const float* __restrict__ k,
                                    const float* __restrict__ v) {
    int z = blockIdx.y;
    const float* src = (z == 0) ? q : (z == 1) ? k : v;
    size_t i4 = (size_t)blockIdx.x * blockDim.x + threadIdx.x;
    float4 val = ((const float4*)src)[i4];
    __nv_bfloat16 h[4], l[4];
    split4(val, h, l);
    *(uint2*)&g_inh[z][i4 * 4] = *(uint2*)h;
    *(uint2*)&g_inl[z][i4 * 4] = *(uint2*)l;
}

// Transposed split of weights: g_wt*[w][n*1024+k] = split(W[k*1024+n])
__global__ void split_weights_kernel(const float* __restrict__ Wq,
                                     const float* __restrict__ Wk,
                                     const float* __restrict__ Wv,
                                     const float* __restrict__ Wo) {
    __shared__ float tile[32][33];
    int w = blockIdx.z;
    const float* W = (w == 0) ? Wq : (w == 1) ? Wk : (w == 2) ? Wv : Wo;
    int n0 = blockIdx.x * 32, k0 = blockIdx.y * 32;
    int tx = threadIdx.x, ty = threadIdx.y;
    #pragma unroll
    for (int r = 0; r < 32; r += 8)
        tile[ty + r][tx] = W[(size_t)(k0 + ty + r) * 1024 + n0 + tx];
    __syncthreads();
    #pragma unroll
    for (int r = 0; r < 32; r += 8) {
        float a = tile[tx][ty + r];
        __nv_bfloat16 hi = __float2bfloat16(a);
        size_t off = (size_t)(n0 + ty + r) * 1024 + k0 + tx;
        g_wth[w][off] = hi;
        g_wtl[w][off] = __float2bfloat16(a - __bfloat162float(hi));
    }
}

// ---------------------------------------------------------------------------
// HMMA bf16-split GEMM: C[4096x1024] = A @ W + bias
// CTA tile 128x128, K-chunks of 32, cp.async double buffer, 8 warps (2x4),
// warp tile 64x32, ldmatrix fragment loads (80B stride = conflict-free).
// Epilogue: fp32 out (Cf) OR bf16 hi/lo split (Ch/Cl).
// ---------------------------------------------------------------------------
#define ROWB      80
#define ARR_B     (128 * ROWB)
#define STAGE_B   (4 * ARR_B)
#define GEMM_SMEM (2 * STAGE_B)

__device__ __forceinline__ void gemm_issue_loads(
    uint32_t sbase, int buf, int tid, int bm, int bn, int k0,
    const __nv_bfloat16* Ah, const __nv_bfloat16* Al,
    const __nv_bfloat16* Bh, const __nv_bfloat16* Bl)
{
    #pragma unroll
    for (int t = 0; t < 2; t++) {
        int id = tid + t * 256;
        int r  = id >> 2;
        int gg = (id & 3) * 8;
        uint32_t so = (uint32_t)buf * STAGE_B + (uint32_t)r * ROWB + gg * 2;
        size_t goA = (size_t)(bm + r) * 1024 + k0 + gg;
        size_t goB = (size_t)(bn + r) * 1024 + k0 + gg;
        cpa16(sbase + so + 0 * ARR_B, Ah + goA);
        cpa16(sbase + so + 1 * ARR_B, Al + goA);
        cpa16(sbase + so + 2 * ARR_B, Bh + goB);
        cpa16(sbase + so + 3 * ARR_B, Bl + goB);
    }
}

__device__ __forceinline__ void gemm_hmma_body(
    const __nv_bfloat16* __restrict__ Ah, const __nv_bfloat16* __restrict__ Al,
    const __nv_bfloat16* __restrict__ Bh, const __nv_bfloat16* __restrict__ Bl,
    const float* __restrict__ bias,
    float* Cf, __nv_bfloat16* Ch, __nv_bfloat16* Cl)
{
    extern __shared__ char dsm[];
    const uint32_t sbase = smem_u32(dsm);
    const int tid  = threadIdx.x;
    const int warp = tid >> 5;
    const int lane = tid & 31;
    const int g    = lane >> 2;
    const int tig  = lane & 3;
    const int wm   = warp >> 2;
    const int wn   = warp & 3;
    const int bm = blockIdx.y * 128;
    const int bn = blockIdx.x * 128;
    const int lane7 = lane & 7;
    const int xr = lane7 + ((lane >> 3) & 1) * 8;
    const int xc = (lane >> 4) * 16;
    const int b16o = ((lane >> 3) & 1) * 16;

    float acc[4][4][4];
    #pragma unroll
    for (int mt = 0; mt < 4; mt++)
        #pragma unroll
        for (int nt = 0; nt < 4; nt++)
            #pragma unroll
            for (int e = 0; e < 4; e++) acc[mt][nt][e] = 0.0f;

    gemm_issue_loads(sbase, 0, tid, bm, bn, 0, Ah, Al, Bh, Bl);
    CPA_COMMIT();

    for (int c = 0; c < 32; c++) {
        const int buf = c & 1;
        if (c + 1 < 32) {
            gemm_issue_loads(sbase, (c + 1) & 1, tid, bm, bn, (c + 1) * 32,
                             Ah, Al, Bh, Bl);
            CPA_COMMIT();
            CPA_WAIT(1);
        } else {
            CPA_WAIT(0);
        }
        __syncthreads();

        const uint32_t sA = sbase + buf * STAGE_B;
        const uint32_t sB = sA + 2 * ARR_B;
        const uint32_t aOff = sA + (wm * 64 + xr) * ROWB + xc;
        const uint32_t bOff = sB + (wn * 32 + lane7) * ROWB + b16o;

        #pragma unroll
        for (int s = 0; s < 2; s++) {
            const int sb = s * 32;
            uint32_t ah[4][4], al[4][4], bh[4][2], bl[4][2];
            #pragma unroll
            for (int mt = 0; mt < 4; mt++) {
                ldm_x4(ah[mt], aOff + mt * 16 * ROWB + sb);
                ldm_x4(al[mt], aOff + ARR_B + mt * 16 * ROWB + sb);
            }
            #pragma unroll
            for (int nt = 0; nt < 4; nt++) {
                ldm_x2(bh[nt], bOff + nt * 8 * ROWB + sb);
                ldm_x2(bl[nt], bOff + ARR_B + nt * 8 * ROWB + sb);
            }
            #pragma unroll
            for (int mt = 0; mt < 4; mt++)
                #pragma unroll
                for (int nt = 0; nt < 4; nt++) {
                    MMA16816(acc[mt][nt], ah[mt], bh[nt]);
                    MMA16816(acc[mt][nt], ah[mt], bl[nt]);
                    MMA16816(acc[mt][nt], al[mt], bh[nt]);
                }
        }
        __syncthreads();
    }

    // epilogue
    #pragma unroll
    for (int nt = 0; nt < 4; nt++) {
        int col = bn + wn * 32 + nt * 8 + tig * 2;
        float2 bb = *(const float2*)&bias[col];
        #pragma unroll
        for (int mt = 0; mt < 4; mt++) {
            int row = bm + wm * 64 + mt * 16 + g;
            float v0 = acc[mt][nt][0] + bb.x, v1 = acc[mt][nt][1] + bb.y;
            float v2 = acc[mt][nt][2] + bb.x, v3 = acc[mt][nt][3] + bb.y;
            if (Cf) {
                *(float2*)&Cf[(size_t)row * 1024 + col] = make_float2(v0, v1);
                *(float2*)&Cf[(size_t)(row + 8) * 1024 + col] = make_float2(v2, v3);
            } else {
                store_split2(Ch, Cl, (size_t)row * 1024 + col, v0, v1);
                store_split2(Ch, Cl, (size_t)(row + 8) * 1024 + col, v2, v3);
            }
        }
    }
}

__global__ __launch_bounds__(256, 1)
void qkv_mma_kernel(const float* __restrict__ bq, const float* __restrict__ bk,
                    const float* __restrict__ bv)
{
    int z = blockIdx.z;
    const float* bias = (z == 0) ? bq : (z == 1) ? bk : bv;
    __nv_bfloat16* Ch = (z == 0) ? g_qh : (z == 1) ? g_kh : g_vh;
    __nv_bfloat16* Cl = (z == 0) ? g_ql : (z == 1) ? g_kl : g_vl;
    gemm_hmma_body(g_inh[z], g_inl[z], g_wth[z], g_wtl[z], bias,
                   nullptr, Ch, Cl);
}

__global__ __launch_bounds__(256, 1)
void o_mma_kernel(const float* __restrict__ bo, float* __restrict__ out)
{
    gemm_hmma_body(g_xh, g_xl, g_wth[3], g_wtl[3], bo, out, nullptr, nullptr);
}

// ---------------------------------------------------------------------------
// HMMA flash-attention. CTA = 128 q-rows x (head,batch); 8 warps, each owns
// 16 q-rows. K/V tiles of 128 rows double-buffered via cp.async. Q fragments
// register-resident. S = Qh*Kh + Qh*Kl + Ql*Kh; P split in-register;
// O += Ph*Vh + Ph*Vl + Pl*Vh. Epilogue writes X as bf16 hi/lo.
// ---------------------------------------------------------------------------
#define ASTR     144
#define AARR     (128 * ASTR)     // 18432
#define ATT_SMEM (10 * AARR)      // Qh,Ql + 2 x (Kh,Kl,Vh,Vl) = 184320

__device__ __forceinline__ void att_load_kv(uint32_t sbase, int tid, int b, int h,
                                            int kt, int buf)
{
    #pragma unroll
    for (int i = 0; i < 16; i++) {
        int id = tid + i * 256;           // 0..4095
        int arr = id >> 10;               // 0=Kh 1=Kl 2=Vh 3=Vl
        int r = (id >> 3) & 127, ck = id & 7;
        const __nv_bfloat16* base =
            (arr == 0) ? g_kh : (arr == 1) ? g_kl : (arr == 2) ? g_vh : g_vl;
        const __nv_bfloat16* src =
            base + (size_t)(b * 1024 + kt * 128 + r) * 1024 + h * 64 + ck * 8;
        cpa16(sbase + (uint32_t)(2 + buf * 4 + arr) * AARR + r * ASTR + ck * 16, src);
    }
    CPA_COMMIT();
}

__global__ __launch_bounds__(256, 1)
void attention_kernel(const void* __restrict__ maskp)
{
    extern __shared__ char att_sm[];
    const uint32_t sbase = smem_u32(att_sm);
    const int tid = threadIdx.x, warp = tid >> 5, lane = tid & 31;
    const int g = lane >> 2, tig = lane & 3;
    const int lane7 = lane & 7;
    const int qt = blockIdx.x, h = blockIdx.y, b = blockIdx.z;

    const bool mbyte = (g_mask_byte != 0);
    const uint8_t*  mask8  = (const uint8_t*)maskp;
    const uint32_t* mask32 = (const uint32_t*)maskp;

    // ---- async load Q tile (hi+lo) ----
    #pragma unroll
    for (int i = 0; i < 8; i++) {
        int id = tid + i * 256;           // 0..2047
        int arr = id >> 10;
        int r = (id >> 3) & 127, ck = id & 7;
        const __nv_bfloat16* src = (arr ? g_ql : g_qh)
            + (size_t)(b * 1024 + qt * 128 + r) * 1024 + h * 64 + ck * 8;
        cpa16(sbase + (uint32_t)arr * AARR + r * ASTR + ck * 16, src);
    }
    CPA_COMMIT();
    att_load_kv(sbase, tid, b, h, 0, 0);
    CPA_WAIT(1);               // Q group done (KV0 still pending)
    __syncthreads();

    // ---- Q fragments, register-resident for the whole kernel ----
    uint32_t qfh[4][4], qfl[4][4];
    {
        const int xr = lane7 + ((lane >> 3) & 1) * 8;
        const int xc = (lane >> 4) * 16;
        uint32_t qb = sbase + (warp * 16 + xr) * ASTR + xc;
        #pragma unroll
        for (int kc = 0; kc < 4; kc++) {
            ldm_x4(qfh[kc], qb + kc * 32);
            ldm_x4(qfl[kc], qb + AARR + kc * 32);
        }
    }

    float O[8][4];
    #pragma unroll
    for (int nt = 0; nt < 8; nt++)
        #pragma unroll
        for (int e = 0; e < 4; e++) O[nt][e] = 0.0f;
    float l0 = 0.f, l1 = 0.f;

    const uint32_t kAdd = lane7 * ASTR + ((lane >> 3) & 1) * 16;
    const uint32_t vAdd = (lane7 + ((lane >> 3) & 1) * 8) * ASTR;
    const size_t mbase = ((size_t)b * 1024 + qt * 128 + warp * 16 + g) * 1024;

    for (int kt = 0; kt < 8; kt++) {
        if (kt < 7) {
            att_load_kv(sbase, tid, b, h, kt + 1, (kt + 1) & 1);
            CPA_WAIT(1);
        } else {
            CPA_WAIT(0);
        }
        __syncthreads();

        const uint32_t kb = sbase + (uint32_t)(2 + (kt & 1) * 4) * AARR;
        const uint32_t vb = kb + 2 * AARR;

        #pragma unroll
        for (int n4 = 0; n4 < 16; n4 += 4) {
            // ---- S = Q K^T for 4 ntiles ----
            float S[4][4];
            #pragma unroll
            for (int u = 0; u < 4; u++)
                #pragma unroll
                for (int e = 0; e < 4; e++) S[u][e] = 0.0f;
            #pragma unroll
            for (int kc = 0; kc < 4; kc++) {
                uint32_t kh_[4][2], kl_[4][2];
                #pragma unroll
                for (int u = 0; u < 4; u++) {
                    uint32_t a = kb + (uint32_t)(n4 + u) * 8 * ASTR + kc * 32 + kAdd;
                    ldm_x2(kh_[u], a);
                    ldm_x2(kl_[u], a + AARR);
                }
                #pragma unroll
                for (int u = 0; u < 4; u++) MMA16816(S[u], qfh[kc], kh_[u]);
                #pragma unroll
                for (int u = 0; u < 4; u++) MMA16816(S[u], qfh[kc], kl_[u]);
                #pragma unroll
                for (int u = 0; u < 4; u++) MMA16816(S[u], qfl[kc], kh_[u]);
            }
            // ---- mask + exp + split into A fragments ----
            uint32_t ph4[4][2], pl4[4][2];
            #pragma unroll
            for (int u = 0; u < 4; u++) {
                int col = kt * 128 + (n4 + u) * 8 + tig * 2;
                size_t m0off = mbase + col;
                size_t m1off = m0off + 8 * 1024;
                uint32_t mm0, mm1, mm2, mm3;
                if (mbyte) {
                    uint16_t w0 = *(const uint16_t*)(mask8 + m0off);
                    uint16_t w1 = *(const uint16_t*)(mask8 + m1off);
                    mm0 = w0 & 0xffu; mm1 = w0 >> 8;
                    mm2 = w1 & 0xffu; mm3 = w1 >> 8;
                } else {
                    uint2 w0 = *(const uint2*)(mask32 + m0off);
                    uint2 w1 = *(const uint2*)(mask32 + m1off);
                    mm0 = w0.x; mm1 = w0.y; mm2 = w1.x; mm3 = w1.y;
                }
                float p0 = mm0 ? 0.f : __expf(S[u][0] * 0.125f);
                float p1 = mm1 ? 0.f : __expf(S[u][1] * 0.125f);
                float p2 = mm2 ? 0.f : __expf(S[u][2] * 0.125f);
                float p3 = mm3 ? 0.f : __expf(S[u][3] * 0.125f);
                l0 += p0 + p1;  l1 += p2 + p3;
                __nv_bfloat16 h0 = __float2bfloat16(p0), h1 = __float2bfloat16(p1);
                __nv_bfloat16 h2 = __float2bfloat16(p2), h3 = __float2bfloat16(p3);
                __nv_bfloat162 t;
                t.x = h0; t.y = h1; ph4[u][0] = *(uint32_t*)&t;
                t.x = h2; t.y = h3; ph4[u][1] = *(uint32_t*)&t;
                t.x = __float2bfloat16(p0 - __bfloat162float(h0));
                t.y = __float2bfloat16(p1 - __bfloat162float(h1));
                pl4[u][0] = *(uint32_t*)&t;
                t.x = __float2bfloat16(p2 - __bfloat162float(h2));
                t.y = __float2bfloat16(p3 - __bfloat162float(h3));
                pl4[u][1] = *(uint32_t*)&t;
            }
            // ---- O += P V for the 2 k16-chunks these 4 ntiles cover ----
            #pragma unroll
            for (int jj = 0; jj < 2; jj++) {
                int jc = n4 / 2 + jj;
                uint32_t ah[4] = {ph4[2*jj][0], ph4[2*jj][1],
                                  ph4[2*jj+1][0], ph4[2*jj+1][1]};
                uint32_t al[4] = {pl4[2*jj][0], pl4[2*jj][1],
                                  pl4[2*jj+1][0], pl4[2*jj+1][1]};
                #pragma unroll
                for (int nt = 0; nt < 8; nt++) {
                    uint32_t vh_[2], vl_[2];
                    uint32_t a = vb + (uint32_t)jc * 16 * ASTR + nt * 16 + vAdd;
                    ldm_x2t(vh_, a);
                    ldm_x2t(vl_, a + AARR);
                    MMA16816(O[nt], ah, vh_);
                    MMA16816(O[nt], ah, vl_);
                    MMA16816(O[nt], al, vh_);
                }
            }
        }
        __syncthreads();
    }

    // ---- normalize rows, write X (bf16 split) ----
    l0 += __shfl_xor_sync(0xffffffffu, l0, 1);
    l0 += __shfl_xor_sync(0xffffffffu, l0, 2);
    l1 += __shfl_xor_sync(0xffffffffu, l1, 1);
    l1 += __shfl_xor_sync(0xffffffffu, l1, 2);
    float inv0 = (l0 > 0.f) ? 1.f / l0 : 0.f;
    float inv1 = (l1 > 0.f) ? 1.f / l1 : 0.f;

    size_t row = (size_t)(b * 1024 + qt * 128 + warp * 16 + g);
    #pragma unroll
    for (int nt = 0; nt < 8; nt++) {
        int col = h * 64 + nt * 8 + tig * 2;
        store_split2(g_xh, g_xl, row * 1024 + col, O[nt][0] * inv0, O[nt][1] * inv0);
        store_split2(g_xh, g_xl, (row + 8) * 1024 + col, O[nt][2] * inv1, O[nt][3] * inv1);
    }
}

// ---------------------------------------------------------------------------
// Launch
// ---------------------------------------------------------------------------
extern "C" void kernel_launch(void* const* d_in, const int* in_sizes, int n_in,
                              void* d_out, int out_size)
{
    const float* query = (const float*)d_in[0];
    const float* key   = (const float*)d_in[1];
    const float* value = (const float*)d_in[2];
    const void*  mask  = d_in[3];
    const float* Wq = (const float*)d_in[4];
    const float* bq = (const float*)d_in[5];
    const float* Wk = (const float*)d_in[6];
    const float* bk = (const float*)d_in[7];
    const float* Wv = (const float*)d_in[8];
    const float* bv = (const float*)d_in[9];
    const float* Wo = (const float*)d_in[10];
    const float* bo = (const float*)d_in[11];
    float* out = (float*)d_out;

    cudaFuncSetAttribute(qkv_mma_kernel,
                         cudaFuncAttributeMaxDynamicSharedMemorySize, GEMM_SMEM);
    cudaFuncSetAttribute(o_mma_kernel,
                         cudaFuncAttributeMaxDynamicSharedMemorySize, GEMM_SMEM);
    cudaFuncSetAttribute(attention_kernel,
                         cudaFuncAttributeMaxDynamicSharedMemorySize, ATT_SMEM);

    detect_mask_kernel<<<1, 256>>>((const uint32_t*)mask);
    split_inputs_kernel<<<dim3(4096, 3), 256>>>(query, key, value);
    split_weights_kernel<<<dim3(32, 32, 4), dim3(32, 8)>>>(Wq, Wk, Wv, Wo);
    qkv_mma_kernel<<<dim3(8, 32, 3), 256, GEMM_SMEM>>>(bq, bk, bv);
    attention_kernel<<<dim3(8, NHEAD, BATCH), 256, ATT_SMEM>>>(mask);
    o_mma_kernel<<<dim3(8, 32, 1), 256, GEMM_SMEM>>>(bo, out);
}